// round 8
// baseline (speedup 1.0000x reference)
#include <cuda_runtime.h>
#include <cuda_bf16.h>
#include <cstdint>

#define NROWS 8192
#define DIM   512
#define SCALE 2.659f
#define QS    64.0f           // fp8 quantization scale
#define INVQ2 (1.0f / 4096.0f)  // 1/(QS*QS)

__device__ uint8_t g_img8[NROWS * DIM];
__device__ uint8_t g_txt8[NROWS * DIM];
__device__ int   g_key[NROWS];
__device__ float g_cnt[NROWS];
__device__ float g_rowsum[NROWS];
__device__ float g_rowdot[NROWS];
__device__ float g_colsum[NROWS];
__device__ float g_coldot[NROWS];
__device__ int   g_done;

// ---------------- asm helpers ----------------
#define MMA_FP8(C, A, B0, B1)                                                \
    asm volatile(                                                            \
        "mma.sync.aligned.m16n8k32.row.col.f32.e4m3.e4m3.f32 "               \
        "{%0,%1,%2,%3}, {%4,%5,%6,%7}, {%8,%9}, {%0,%1,%2,%3};"              \
        : "+f"((C)[0]), "+f"((C)[1]), "+f"((C)[2]), "+f"((C)[3])             \
        : "r"((A)[0]), "r"((A)[1]), "r"((A)[2]), "r"((A)[3]),                \
          "r"(B0), "r"(B1))

#define LDSM4(R, ADDR)                                                       \
    asm volatile("ldmatrix.sync.aligned.m8n8.x4.shared.b16 {%0,%1,%2,%3}, [%4];" \
                 : "=r"((R)[0]), "=r"((R)[1]), "=r"((R)[2]), "=r"((R)[3])    \
                 : "r"(ADDR))

#define CP_ASYNC16(dst, src)                                                 \
    asm volatile("cp.async.cg.shared.global [%0], [%1], 16;"                 \
                 :: "r"(dst), "l"(src))
#define CP_COMMIT() asm volatile("cp.async.commit_group;" ::: "memory")
#define CP_WAIT(N)  asm volatile("cp.async.wait_group %0;" :: "n"(N) : "memory")

__device__ __forceinline__ uint32_t pack_e4m3x4(float a, float b, float c, float d) {
    uint16_t lo, hi;
    // first PTX source operand lands in the HIGH byte -> pass later-k first
    asm("cvt.rn.satfinite.e4m3x2.f32 %0, %1, %2;" : "=h"(lo) : "f"(b), "f"(a));
    asm("cvt.rn.satfinite.e4m3x2.f32 %0, %1, %2;" : "=h"(hi) : "f"(d), "f"(c));
    return (uint32_t)lo | ((uint32_t)hi << 16);
}

// ---------------------------------------------------------------------------
// Prep kernel: grid (NROWS+1, 2), 128 threads.
//   blockIdx.x < NROWS  -> L2-normalize one row, quantize to e4m3 (x * 64).
//   blockIdx.x == NROWS, y == 0 -> label prep (dtype sniff, keys, counts,
//   zero accumulators).
// ---------------------------------------------------------------------------
__global__ void prep_kernel(const float* __restrict__ text,
                            const float* __restrict__ image,
                            const int* __restrict__ p) {
    int tid = threadIdx.x;
    if (blockIdx.x == NROWS) {
        if (blockIdx.y != 0) return;
        __shared__ int viol;
        __shared__ int h[128];
        if (tid == 0) { viol = 0; g_done = 0; }
        h[tid] = 0;
        __syncthreads();
        int v = 0;
        for (int i = tid; i < NROWS / 2; i += 128) {
            int hiw = p[2 * i + 1];
            if (hiw != 0 && hiw != -1) v = 1;
        }
        if (v) atomicAdd(&viol, 1);
        __syncthreads();
        bool is64 = (viol == 0);
        for (int i = tid; i < NROWS; i += 128) {
            int l = is64 ? p[2 * i] : p[i];
            g_key[i] = (l >= 0 && l < 128) ? l : (1 << 20) + i;
            if (l >= 0 && l < 128) atomicAdd(&h[l], 1);
            g_rowsum[i] = 0.0f; g_rowdot[i] = 0.0f;
            g_colsum[i] = 0.0f; g_coldot[i] = 0.0f;
        }
        __syncthreads();
        for (int i = tid; i < NROWS; i += 128) {
            int k = g_key[i];
            g_cnt[i] = (k < 128) ? (float)h[k] : 1.0f;
        }
        return;
    }

    int row = blockIdx.x;
    const float* src = blockIdx.y ? text : image;
    uint8_t* dst = blockIdx.y ? g_txt8 : g_img8;
    int lane = tid & 31, wid = tid >> 5;

    float4 v = ((const float4*)(src + (size_t)row * DIM))[tid];
    float ss = v.x * v.x + v.y * v.y + v.z * v.z + v.w * v.w;
#pragma unroll
    for (int o = 16; o; o >>= 1) ss += __shfl_xor_sync(0xffffffffu, ss, o);
    __shared__ float wss[4];
    if (lane == 0) wss[wid] = ss;
    __syncthreads();
    float tot = wss[0] + wss[1] + wss[2] + wss[3];
    float inv = QS / fmaxf(sqrtf(tot), 1e-12f);

    ((uint32_t*)(dst + (size_t)row * DIM))[tid] =
        pack_e4m3x4(v.x * inv, v.y * inv, v.z * inv, v.w * inv);
}

// ---------------------------------------------------------------------------
// Main kernel: single pass over S = img_n @ txt_n^T in fp8 (e4m3).
// grid (64, 16), 512 threads (16 warps = 4m x 4n), warp tile 32x64.
// x = 128-row m-block, y = 512-col n-group processed as 2 halves of 256.
// A panel (128x512 fp8 = 64KB) resident; B 3-stage cp.async ring
// (32KB/stage, chunk = [256 cols][128 k]), prefetch distance 2, wait(1).
// ---------------------------------------------------------------------------
__global__ __launch_bounds__(512, 1)
void unicl_gemm_kernel(float* __restrict__ out) {
    extern __shared__ char sm[];
    uint32_t sbase = (uint32_t)__cvta_generic_to_shared(sm);
    const uint32_t As_u = sbase;               // [4 kchunks][128 rows][128 B]
    const uint32_t Bs_u = sbase + 65536u;      // 3 stages x [256 cols][128 B]
    int*   keys_s = (int*)(sm + 163840);       // 512
    float* row_se = (float*)(sm + 165888);     // 128
    float* row_dt = (float*)(sm + 166400);     // 128
    float* col_se = (float*)(sm + 166912);     // 512
    float* col_dt = (float*)(sm + 168960);     // 512
    int*   flag_s = (int*)(sm + 171008);
    float* red_s  = (float*)(sm + 171008);     // 512 floats (reuse)

    int tid = threadIdx.x, lane = tid & 31, wid = tid >> 5;
    int gm0 = blockIdx.x * 128;
    int n0  = blockIdx.y * 512;
    const uint8_t* Ag = g_img8;
    const uint8_t* Bg = g_txt8;

    for (int i = tid; i < 128; i += 512) { row_se[i] = 0.0f; row_dt[i] = 0.0f; }
    for (int i = tid; i < 512; i += 512) {
        col_se[i] = 0.0f; col_dt[i] = 0.0f;
        keys_s[i] = g_key[n0 + i];
    }

    // --- A prologue: 128x512B into [kc][128][128B] swizzled ---
#pragma unroll
    for (int q = 0; q < 8; q++) {
        int idx = tid + q * 512;
        int kc = idx >> 10, row = (idx >> 3) & 127, ch = idx & 7;
        const void* src = Ag + (size_t)(gm0 + row) * DIM + kc * 128 + ch * 16;
        uint32_t dst = As_u + kc * 16384 + row * 128 + ((ch ^ (row & 7)) << 4);
        CP_ASYNC16(dst, src);
    }
    CP_COMMIT();

    auto issueB = [&](int gs) {
        int t = gs >> 2, kc = gs & 3;
        const uint8_t* bsrc = Bg + (size_t)(n0 + t * 256) * DIM + kc * 128;
        uint32_t bdst = Bs_u + (uint32_t)(gs % 3) * 32768u;
#pragma unroll
        for (int q = 0; q < 4; q++) {
            int idx = tid + q * 512;
            int row = idx >> 3, ch = idx & 7;
            CP_ASYNC16(bdst + row * 128 + ((ch ^ (row & 7)) << 4),
                       bsrc + (size_t)row * DIM + ch * 16);
        }
    };
    issueB(0); CP_COMMIT();
    issueB(1); CP_COMMIT();

    // --- warp geometry: 4 m-warps (32 rows) x 4 n-warps (64 cols) ---
    int warp_m = (wid & 3) * 32;
    int warp_n = (wid >> 2) * 64;
    int g = lane >> 2, tig = lane & 3;
    uint32_t a_off = (uint32_t)(warp_m + (lane & 15)) * 128;
    uint32_t hiA = (uint32_t)(lane >> 4);
    uint32_t swA = (uint32_t)(lane & 7);
    int rB0 = warp_n + (lane & 7) + ((lane >> 4) << 3);
    uint32_t b_off = (uint32_t)rB0 * 128;
    uint32_t hiB = (uint32_t)((lane >> 3) & 1);
    uint32_t swB = (uint32_t)(lane & 7);

    int mykey[4];
#pragma unroll
    for (int ri = 0; ri < 4; ri++)
        mykey[ri] = g_key[gm0 + warp_m + g + ri * 8];

    float rse[4] = {0.f, 0.f, 0.f, 0.f};
    float rdt[4] = {0.f, 0.f, 0.f, 0.f};
    const float K2q = SCALE * 1.44269504f * INVQ2;  // per-c multiplier
    const float K2b = SCALE * 1.44269504f;          // bias (exp(s - SCALE))

    for (int t = 0; t < 2; t++) {
        float c[2][8][4];
#pragma unroll
        for (int mf = 0; mf < 2; mf++)
#pragma unroll
            for (int nf = 0; nf < 8; nf++)
#pragma unroll
                for (int e = 0; e < 4; e++) c[mf][nf][e] = 0.0f;

#pragma unroll 1
        for (int kc = 0; kc < 4; kc++) {
            int gs = t * 4 + kc;
            if (gs < 7) { CP_WAIT(1); } else { CP_WAIT(0); }
            __syncthreads();   // all warps done with chunk gs-1 -> its stage reusable
            if (gs + 2 < 8) { issueB(gs + 2); CP_COMMIT(); }

            uint32_t Ab = As_u + kc * 16384;
            uint32_t Bb = Bs_u + (uint32_t)(gs % 3) * 32768u;
#pragma unroll
            for (int k32 = 0; k32 < 4; k32++) {
                uint32_t a0[4], a1[4], b[4][4];
                uint32_t cA = ((k32 * 2 + hiA) ^ swA) << 4;
                LDSM4(a0, Ab + a_off + cA);
                LDSM4(a1, Ab + a_off + 2048 + cA);
                uint32_t cB = ((k32 * 2 + hiB) ^ swB) << 4;
                LDSM4(b[0], Bb + b_off + cB);
                LDSM4(b[1], Bb + b_off + 2048 + cB);
                LDSM4(b[2], Bb + b_off + 4096 + cB);
                LDSM4(b[3], Bb + b_off + 6144 + cB);
#pragma unroll
                for (int j = 0; j < 4; j++) {
                    MMA_FP8(c[0][2 * j],     a0, b[j][0], b[j][1]);
                    MMA_FP8(c[0][2 * j + 1], a0, b[j][2], b[j][3]);
                    MMA_FP8(c[1][2 * j],     a1, b[j][0], b[j][1]);
                    MMA_FP8(c[1][2 * j + 1], a1, b[j][2], b[j][3]);
                }
            }
        }

        // --- epilogue for n-half t ---
        float cse[16], cdt[16];
#pragma unroll
        for (int p = 0; p < 16; p++) { cse[p] = 0.0f; cdt[p] = 0.0f; }
        const int* ks = keys_s + t * 256 + warp_n;
#pragma unroll
        for (int mf = 0; mf < 2; mf++) {
#pragma unroll
            for (int nf = 0; nf < 8; nf++) {
#pragma unroll
                for (int e = 0; e < 4; e++) {
                    float cv = c[mf][nf][e];   // ~4096 * dot
                    float ex;
                    asm("ex2.approx.ftz.f32 %0, %1;" : "=f"(ex)
                        : "f"(fmaf(cv, K2q, -K2b)));
                    int ri = mf * 2 + (e >> 1);
                    int p  = nf * 2 + (e & 1);
                    rse[ri] += ex;
                    cse[p]  += ex;
                    int key = ks[nf * 8 + tig * 2 + (e & 1)];
                    if (key == mykey[ri]) { rdt[ri] += cv; cdt[p] += cv; }
                }
            }
        }
#pragma unroll
        for (int p = 0; p < 16; p++) {
            cse[p] += __shfl_xor_sync(0xffffffffu, cse[p], 4);
            cse[p] += __shfl_xor_sync(0xffffffffu, cse[p], 8);
            cse[p] += __shfl_xor_sync(0xffffffffu, cse[p], 16);
            cdt[p] += __shfl_xor_sync(0xffffffffu, cdt[p], 4);
            cdt[p] += __shfl_xor_sync(0xffffffffu, cdt[p], 8);
            cdt[p] += __shfl_xor_sync(0xffffffffu, cdt[p], 16);
        }
#pragma unroll
        for (int q = 0; q < 2; q++) {
            int p = g * 2 + q;
            int cidx = t * 256 + warp_n + (p >> 1) * 8 + tig * 2 + (p & 1);
            atomicAdd(&col_se[cidx], cse[p]);
            atomicAdd(&col_dt[cidx], cdt[p]);
        }
    }

    // --- row reduction + CTA flush ---
#pragma unroll
    for (int ri = 0; ri < 4; ri++) {
        float v = rse[ri];
        v += __shfl_xor_sync(0xffffffffu, v, 1);
        v += __shfl_xor_sync(0xffffffffu, v, 2);
        float w = rdt[ri];
        w += __shfl_xor_sync(0xffffffffu, w, 1);
        w += __shfl_xor_sync(0xffffffffu, w, 2);
        if (tig == 0) {
            atomicAdd(&row_se[warp_m + g + ri * 8], v);
            atomicAdd(&row_dt[warp_m + g + ri * 8], w);
        }
    }
    __syncthreads();
    for (int i = tid; i < 128; i += 512) {
        atomicAdd(&g_rowsum[gm0 + i], row_se[i]);
        atomicAdd(&g_rowdot[gm0 + i], row_dt[i]);
    }
    for (int i = tid; i < 512; i += 512) {
        atomicAdd(&g_colsum[n0 + i], col_se[i]);
        atomicAdd(&g_coldot[n0 + i], col_dt[i]);
    }

    // --- last CTA computes the final loss ---
    __threadfence();
    __syncthreads();
    if (tid == 0) {
        int prev = atomicAdd(&g_done, 1);
        flag_s[0] = (prev == gridDim.x * gridDim.y - 1) ? 1 : 0;
    }
    __syncthreads();
    if (flag_s[0]) {
        __threadfence();
        float s = 0.0f;
        for (int i = tid; i < NROWS; i += 512) {
            float inv = (SCALE * INVQ2) / g_cnt[i];   // dot accums carry QS^2
            s += 2.0f * SCALE + logf(g_rowsum[i]) + logf(g_colsum[i])
                 - (g_rowdot[i] + g_coldot[i]) * inv;
        }
        __syncthreads();
        red_s[tid] = s;
        __syncthreads();
        for (int o = 256; o; o >>= 1) {
            if (tid < o) red_s[tid] += red_s[tid + o];
            __syncthreads();
        }
        if (tid == 0) out[0] = red_s[0] * (1.0f / (2.0f * NROWS));
    }
}

// ---------------------------------------------------------------------------
extern "C" void kernel_launch(void* const* d_in, const int* in_sizes, int n_in,
                              void* d_out, int out_size) {
    const float* text   = (const float*)d_in[0];
    const float* image  = (const float*)d_in[1];
    const int*   labels = (const int*)d_in[2];
    float* out = (float*)d_out;

    prep_kernel<<<dim3(NROWS + 1, 2), 128>>>(text, image, labels);

    int smem_bytes = 173056;
    cudaFuncSetAttribute(unicl_gemm_kernel,
                         cudaFuncAttributeMaxDynamicSharedMemorySize, smem_bytes);
    unicl_gemm_kernel<<<dim3(64, 16), 512, smem_bytes>>>(out);
}

// round 9
// speedup vs baseline: 1.1746x; 1.1746x over previous
#include <cuda_runtime.h>
#include <cuda_bf16.h>
#include <cstdint>

#define NROWS 8192
#define DIM   512
#define SCALE 2.659f
#define QS    64.0f             // fp8 quantization scale
#define INVQ2 (1.0f / 4096.0f)  // 1/(QS*QS)

__device__ uint8_t g_img8[NROWS * DIM];
__device__ uint8_t g_txt8[NROWS * DIM];
__device__ int   g_key[NROWS];
__device__ float g_cnt[NROWS];
__device__ float g_rowsum[NROWS];
__device__ float g_rowdot[NROWS];
__device__ float g_colsum[NROWS];
__device__ float g_coldot[NROWS];
__device__ int   g_done;

// ---------------- asm helpers ----------------
#define MMA_FP8(C, A, B0, B1)                                                \
    asm volatile(                                                            \
        "mma.sync.aligned.m16n8k32.row.col.f32.e4m3.e4m3.f32 "               \
        "{%0,%1,%2,%3}, {%4,%5,%6,%7}, {%8,%9}, {%0,%1,%2,%3};"              \
        : "+f"((C)[0]), "+f"((C)[1]), "+f"((C)[2]), "+f"((C)[3])             \
        : "r"((A)[0]), "r"((A)[1]), "r"((A)[2]), "r"((A)[3]),                \
          "r"(B0), "r"(B1))

#define LDSM4(R, ADDR)                                                       \
    asm volatile("ldmatrix.sync.aligned.m8n8.x4.shared.b16 {%0,%1,%2,%3}, [%4];" \
                 : "=r"((R)[0]), "=r"((R)[1]), "=r"((R)[2]), "=r"((R)[3])    \
                 : "r"(ADDR))

#define CP_ASYNC16(dst, src)                                                 \
    asm volatile("cp.async.cg.shared.global [%0], [%1], 16;"                 \
                 :: "r"(dst), "l"(src))
#define CP_COMMIT() asm volatile("cp.async.commit_group;" ::: "memory")
#define CP_WAIT(N)  asm volatile("cp.async.wait_group %0;" :: "n"(N) : "memory")

__device__ __forceinline__ uint32_t pack_e4m3x4(float a, float b, float c, float d) {
    uint16_t lo, hi;
    asm("cvt.rn.satfinite.e4m3x2.f32 %0, %1, %2;" : "=h"(lo) : "f"(b), "f"(a));
    asm("cvt.rn.satfinite.e4m3x2.f32 %0, %1, %2;" : "=h"(hi) : "f"(d), "f"(c));
    return (uint32_t)lo | ((uint32_t)hi << 16);
}

// ---------------------------------------------------------------------------
// Prep kernel: grid (NROWS+1, 2), 128 threads.
//   blockIdx.x < NROWS  -> L2-normalize one row, quantize to e4m3 (x * 64).
//   blockIdx.x == NROWS, y == 0 -> label prep.
// ---------------------------------------------------------------------------
__global__ void prep_kernel(const float* __restrict__ text,
                            const float* __restrict__ image,
                            const int* __restrict__ p) {
    int tid = threadIdx.x;
    if (blockIdx.x == NROWS) {
        if (blockIdx.y != 0) return;
        __shared__ int viol;
        __shared__ int h[128];
        if (tid == 0) { viol = 0; g_done = 0; }
        h[tid] = 0;
        __syncthreads();
        int v = 0;
        for (int i = tid; i < NROWS / 2; i += 128) {
            int hiw = p[2 * i + 1];
            if (hiw != 0 && hiw != -1) v = 1;
        }
        if (v) atomicAdd(&viol, 1);
        __syncthreads();
        bool is64 = (viol == 0);
        for (int i = tid; i < NROWS; i += 128) {
            int l = is64 ? p[2 * i] : p[i];
            g_key[i] = (l >= 0 && l < 128) ? l : (1 << 20) + i;
            if (l >= 0 && l < 128) atomicAdd(&h[l], 1);
            g_rowsum[i] = 0.0f; g_rowdot[i] = 0.0f;
            g_colsum[i] = 0.0f; g_coldot[i] = 0.0f;
        }
        __syncthreads();
        for (int i = tid; i < NROWS; i += 128) {
            int k = g_key[i];
            g_cnt[i] = (k < 128) ? (float)h[k] : 1.0f;
        }
        return;
    }

    int row = blockIdx.x;
    const float* src = blockIdx.y ? text : image;
    uint8_t* dst = blockIdx.y ? g_txt8 : g_img8;
    int lane = tid & 31, wid = tid >> 5;

    float4 v = ((const float4*)(src + (size_t)row * DIM))[tid];
    float ss = v.x * v.x + v.y * v.y + v.z * v.z + v.w * v.w;
#pragma unroll
    for (int o = 16; o; o >>= 1) ss += __shfl_xor_sync(0xffffffffu, ss, o);
    __shared__ float wss[4];
    if (lane == 0) wss[wid] = ss;
    __syncthreads();
    float tot = wss[0] + wss[1] + wss[2] + wss[3];
    float inv = QS / fmaxf(sqrtf(tot), 1e-12f);

    ((uint32_t*)(dst + (size_t)row * DIM))[tid] =
        pack_e4m3x4(v.x * inv, v.y * inv, v.z * inv, v.w * inv);
}

// ---------------------------------------------------------------------------
// Main kernel: single pass over S = img_n @ txt_n^T in fp8 (e4m3).
// grid (64, 64), 256 threads (8 warps = 4m x 2n), warp tile 32x64,
// CTA tile 128 rows x 128 cols. TWO CTAs co-resident per SM (~102KB smem,
// 128 regs) so barrier/load stalls of one CTA are hidden by the other.
// A panel (128x512B) resident; B 2-stage ring (16KB/stage, chunk = [128][128k]).
// ---------------------------------------------------------------------------
__global__ __launch_bounds__(256, 2)
void unicl_gemm_kernel(float* __restrict__ out) {
    extern __shared__ char sm[];
    uint32_t sbase = (uint32_t)__cvta_generic_to_shared(sm);
    const uint32_t As_u = sbase;                // [4 kc][128 rows][128 B]
    const uint32_t Bs_u = sbase + 65536u;       // 2 stages x [128 cols][128 B]
    int*   keys_s = (int*)(sm + 98304);         // 128
    float* row_se = (float*)(sm + 98816);       // 128
    float* row_dt = (float*)(sm + 99328);       // 128
    float* col_se = (float*)(sm + 99840);       // 128
    float* col_dt = (float*)(sm + 100352);      // 128
    int*   flag_s = (int*)(sm + 100864);
    float* red_s  = (float*)(sm + 100864);      // 256 floats (reuse)

    int tid = threadIdx.x, lane = tid & 31, wid = tid >> 5;
    int gm0 = blockIdx.x * 128;
    int n0  = blockIdx.y * 128;
    const uint8_t* Ag = g_img8;
    const uint8_t* Bg = g_txt8;

    for (int i = tid; i < 128; i += 256) {
        row_se[i] = 0.0f; row_dt[i] = 0.0f;
        col_se[i] = 0.0f; col_dt[i] = 0.0f;
        keys_s[i] = g_key[n0 + i];
    }

    // --- A prologue: 128x512B into [kc][128][128B] swizzled ---
#pragma unroll
    for (int q = 0; q < 16; q++) {
        int idx = tid + q * 256;
        int kc = idx >> 10, row = (idx >> 3) & 127, ch = idx & 7;
        const void* src = Ag + (size_t)(gm0 + row) * DIM + kc * 128 + ch * 16;
        uint32_t dst = As_u + kc * 16384 + row * 128 + ((ch ^ (row & 7)) << 4);
        CP_ASYNC16(dst, src);
    }
    CP_COMMIT();

    auto issueB = [&](int kc) {
        const uint8_t* bsrc = Bg + (size_t)n0 * DIM + kc * 128;
        uint32_t bdst = Bs_u + (uint32_t)(kc & 1) * 16384u;
#pragma unroll
        for (int q = 0; q < 4; q++) {
            int idx = tid + q * 256;
            int row = idx >> 3, ch = idx & 7;
            CP_ASYNC16(bdst + row * 128 + ((ch ^ (row & 7)) << 4),
                       bsrc + (size_t)row * DIM + ch * 16);
        }
    };
    issueB(0); CP_COMMIT();

    // --- warp geometry: 4 m-warps (32 rows) x 2 n-warps (64 cols) ---
    int warp_m = (wid & 3) * 32;
    int warp_n = (wid >> 2) * 64;
    int g = lane >> 2, tig = lane & 3;
    uint32_t a_off = (uint32_t)(warp_m + (lane & 15)) * 128;
    uint32_t hiA = (uint32_t)(lane >> 4);
    uint32_t swA = (uint32_t)(lane & 7);
    int rB0 = warp_n + (lane & 7) + ((lane >> 4) << 3);
    uint32_t b_off = (uint32_t)rB0 * 128;
    uint32_t hiB = (uint32_t)((lane >> 3) & 1);
    uint32_t swB = (uint32_t)(lane & 7);

    int mykey[4];
#pragma unroll
    for (int ri = 0; ri < 4; ri++)
        mykey[ri] = g_key[gm0 + warp_m + g + ri * 8];

    float rse[4] = {0.f, 0.f, 0.f, 0.f};
    float rdt[4] = {0.f, 0.f, 0.f, 0.f};
    const float K2q = SCALE * 1.44269504f * INVQ2;
    const float K2b = SCALE * 1.44269504f;

    float c[2][8][4];
#pragma unroll
    for (int mf = 0; mf < 2; mf++)
#pragma unroll
        for (int nf = 0; nf < 8; nf++)
#pragma unroll
            for (int e = 0; e < 4; e++) c[mf][nf][e] = 0.0f;

#pragma unroll 1
    for (int kc = 0; kc < 4; kc++) {
        CP_WAIT(0);
        __syncthreads();   // all warps done with prior chunk -> other stage free
        if (kc + 1 < 4) { issueB(kc + 1); CP_COMMIT(); }

        uint32_t Ab = As_u + kc * 16384;
        uint32_t Bb = Bs_u + (uint32_t)(kc & 1) * 16384u;
#pragma unroll
        for (int k32 = 0; k32 < 4; k32++) {
            uint32_t a0[4], a1[4], b[4][4];
            uint32_t cA = ((k32 * 2 + hiA) ^ swA) << 4;
            LDSM4(a0, Ab + a_off + cA);
            LDSM4(a1, Ab + a_off + 2048 + cA);
            uint32_t cB = ((k32 * 2 + hiB) ^ swB) << 4;
            LDSM4(b[0], Bb + b_off + cB);
            LDSM4(b[1], Bb + b_off + 2048 + cB);
            LDSM4(b[2], Bb + b_off + 4096 + cB);
            LDSM4(b[3], Bb + b_off + 6144 + cB);
#pragma unroll
            for (int j = 0; j < 4; j++) {
                MMA_FP8(c[0][2 * j],     a0, b[j][0], b[j][1]);
                MMA_FP8(c[0][2 * j + 1], a0, b[j][2], b[j][3]);
                MMA_FP8(c[1][2 * j],     a1, b[j][0], b[j][1]);
                MMA_FP8(c[1][2 * j + 1], a1, b[j][2], b[j][3]);
            }
        }
    }

    // --- epilogue ---
    float cse[16], cdt[16];
#pragma unroll
    for (int p = 0; p < 16; p++) { cse[p] = 0.0f; cdt[p] = 0.0f; }
    const int* ks = keys_s + warp_n;
#pragma unroll
    for (int mf = 0; mf < 2; mf++) {
#pragma unroll
        for (int nf = 0; nf < 8; nf++) {
#pragma unroll
            for (int e = 0; e < 4; e++) {
                float cv = c[mf][nf][e];   // dot * QS^2
                float ex;
                asm("ex2.approx.ftz.f32 %0, %1;" : "=f"(ex)
                    : "f"(fmaf(cv, K2q, -K2b)));
                int ri = mf * 2 + (e >> 1);
                int p  = nf * 2 + (e & 1);
                rse[ri] += ex;
                cse[p]  += ex;
                int key = ks[nf * 8 + tig * 2 + (e & 1)];
                if (key == mykey[ri]) { rdt[ri] += cv; cdt[p] += cv; }
            }
        }
    }
#pragma unroll
    for (int p = 0; p < 16; p++) {
        cse[p] += __shfl_xor_sync(0xffffffffu, cse[p], 4);
        cse[p] += __shfl_xor_sync(0xffffffffu, cse[p], 8);
        cse[p] += __shfl_xor_sync(0xffffffffu, cse[p], 16);
        cdt[p] += __shfl_xor_sync(0xffffffffu, cdt[p], 4);
        cdt[p] += __shfl_xor_sync(0xffffffffu, cdt[p], 8);
        cdt[p] += __shfl_xor_sync(0xffffffffu, cdt[p], 16);
    }
#pragma unroll
    for (int q = 0; q < 2; q++) {
        int p = g * 2 + q;
        int cidx = warp_n + (p >> 1) * 8 + tig * 2 + (p & 1);
        atomicAdd(&col_se[cidx], cse[p]);
        atomicAdd(&col_dt[cidx], cdt[p]);
    }

    // --- row reduction + CTA flush ---
#pragma unroll
    for (int ri = 0; ri < 4; ri++) {
        float v = rse[ri];
        v += __shfl_xor_sync(0xffffffffu, v, 1);
        v += __shfl_xor_sync(0xffffffffu, v, 2);
        float w = rdt[ri];
        w += __shfl_xor_sync(0xffffffffu, w, 1);
        w += __shfl_xor_sync(0xffffffffu, w, 2);
        if (tig == 0) {
            atomicAdd(&row_se[warp_m + g + ri * 8], v);
            atomicAdd(&row_dt[warp_m + g + ri * 8], w);
        }
    }
    __syncthreads();
    for (int i = tid; i < 128; i += 256) {
        atomicAdd(&g_rowsum[gm0 + i], row_se[i]);
        atomicAdd(&g_rowdot[gm0 + i], row_dt[i]);
        atomicAdd(&g_colsum[n0 + i], col_se[i]);
        atomicAdd(&g_coldot[n0 + i], col_dt[i]);
    }

    // --- last CTA computes the final loss ---
    __threadfence();
    __syncthreads();
    if (tid == 0) {
        int prev = atomicAdd(&g_done, 1);
        flag_s[0] = (prev == gridDim.x * gridDim.y - 1) ? 1 : 0;
    }
    __syncthreads();
    if (flag_s[0]) {
        __threadfence();
        float s = 0.0f;
        for (int i = tid; i < NROWS; i += 256) {
            float inv = (SCALE * INVQ2) / g_cnt[i];
            s += 2.0f * SCALE + logf(g_rowsum[i]) + logf(g_colsum[i])
                 - (g_rowdot[i] + g_coldot[i]) * inv;
        }
        __syncthreads();
        red_s[tid] = s;
        __syncthreads();
        for (int o = 128; o; o >>= 1) {
            if (tid < o) red_s[tid] += red_s[tid + o];
            __syncthreads();
        }
        if (tid == 0) out[0] = red_s[0] * (1.0f / (2.0f * NROWS));
    }
}

// ---------------------------------------------------------------------------
extern "C" void kernel_launch(void* const* d_in, const int* in_sizes, int n_in,
                              void* d_out, int out_size) {
    const float* text   = (const float*)d_in[0];
    const float* image  = (const float*)d_in[1];
    const int*   labels = (const int*)d_in[2];
    float* out = (float*)d_out;

    prep_kernel<<<dim3(NROWS + 1, 2), 128>>>(text, image, labels);

    int smem_bytes = 101888;
    cudaFuncSetAttribute(unicl_gemm_kernel,
                         cudaFuncAttributeMaxDynamicSharedMemorySize, smem_bytes);
    unicl_gemm_kernel<<<dim3(64, 64), 256, smem_bytes>>>(out);
}